// round 1
// baseline (speedup 1.0000x reference)
#include <cuda_runtime.h>

#define NN 100000
#define NE 1200000
#define EPSF 1e-5f

// ---------------- scratch (device globals; no allocations) ----------------
__device__ float g_deg[NN];
__device__ float g_agg1[NN * 64];
__device__ float g_hpre[NN * 128];
__device__ float g_t2[NN * 64];
__device__ float g_p2[NN * 64];
__device__ float g_agg2[NN * 64];
__device__ float g_x0pre[NN * 64];
__device__ float g_s1[128], g_ss1[128];
__device__ float g_s2[64], g_ss2[64];
__device__ int g_is64;

// ---------------- K0: zero scratch + edge dtype detection ----------------
__global__ void zero_kernel(const int* __restrict__ ei) {
    long long i = (long long)blockIdx.x * blockDim.x + threadIdx.x;
    long long stride = (long long)gridDim.x * blockDim.x;
    for (long long j = i; j < (long long)NN * 64; j += stride) {
        g_agg1[j] = 0.f;
        g_agg2[j] = 0.f;
    }
    for (long long j = i; j < NN; j += stride) g_deg[j] = 0.f;
    if (i < 128) { g_s1[i] = 0.f; g_ss1[i] = 0.f; }
    if (i < 64)  { g_s2[i] = 0.f; g_ss2[i] = 0.f; }
    if (i == 0) {
        // int64 indices < 100000 -> every odd 32-bit word (high half) is 0.
        int z = 0;
        #pragma unroll
        for (int k = 1; k < 16; k += 2) z |= ei[k];
        g_is64 = (z == 0) ? 1 : 0;
    }
}

// ---------------- K1: scatter x -> agg1, degree ----------------
__global__ __launch_bounds__(256) void scatter1_kernel(const float* __restrict__ x,
                                                       const int* __restrict__ ei) {
    long long tid = (long long)blockIdx.x * 256 + threadIdx.x;
    int e = (int)(tid >> 6);
    if (e >= NE) return;
    int c = (int)(tid & 63);
    int s, d;
    if (g_is64) { s = ei[2 * e]; d = ei[2 * (NE + e)]; }
    else        { s = ei[e];     d = ei[NE + e]; }
    atomicAdd(&g_agg1[d * 64 + c], x[s * 64 + c]);
    if (c == 0) atomicAdd(&g_deg[d], 1.0f);
}

// ---------------- K2: layer-1 GEMMs + bias + BN1 stats ----------------
// hpre[i][o] = sum_k mean1[i][k]*Wl1[o][k] + x[i][k]*Wr1[o][k] + bl1[o]
__global__ __launch_bounds__(256) void layer1_kernel(const float* __restrict__ x,
                                                     const float* __restrict__ Wl1,
                                                     const float* __restrict__ bl1,
                                                     const float* __restrict__ Wr1) {
    __shared__ float in_s[32][128];   // [node][k]; k<64: mean1, k>=64: x
    __shared__ float w_s[32][132];    // transposed weight chunk [kk][out]
    __shared__ float s_sh[128], ss_sh[128];

    int t = threadIdx.x;
    int node0 = blockIdx.x * 32;

    for (int idx = t; idx < 32 * 128; idx += 256) {
        int ni = idx >> 7, k = idx & 127;
        int node = node0 + ni;
        float v;
        if (k < 64) v = g_agg1[node * 64 + k] / fmaxf(g_deg[node], 1.0f);
        else        v = x[node * 64 + (k - 64)];
        in_s[ni][k] = v;
    }
    if (t < 128) { s_sh[t] = 0.f; ss_sh[t] = 0.f; }

    int tx = t & 31, ty = t >> 5;   // tx -> 4 outs, ty -> 4 nodes
    float acc[4][4] = {};

    for (int kc = 0; kc < 4; kc++) {
        __syncthreads();
        for (int idx = t; idx < 32 * 128; idx += 256) {
            int o = idx >> 5, kk = idx & 31;
            int kt = kc * 32 + kk;
            float wv = (kt < 64) ? Wl1[o * 64 + kt] : Wr1[o * 64 + (kt - 64)];
            w_s[kk][o] = wv;
        }
        __syncthreads();
        #pragma unroll
        for (int kk = 0; kk < 32; kk++) {
            float4 wv4 = *(const float4*)&w_s[kk][tx * 4];
            float w[4] = {wv4.x, wv4.y, wv4.z, wv4.w};
            int kt = kc * 32 + kk;
            float a[4];
            #pragma unroll
            for (int i = 0; i < 4; i++) a[i] = in_s[ty * 4 + i][kt];
            #pragma unroll
            for (int i = 0; i < 4; i++)
                #pragma unroll
                for (int j = 0; j < 4; j++) acc[i][j] += a[i] * w[j];
        }
    }

    float b[4];
    #pragma unroll
    for (int j = 0; j < 4; j++) b[j] = bl1[tx * 4 + j];

    float ps[4] = {0, 0, 0, 0}, pss[4] = {0, 0, 0, 0};
    #pragma unroll
    for (int i = 0; i < 4; i++) {
        int node = node0 + ty * 4 + i;
        float4 hv;
        hv.x = acc[i][0] + b[0];
        hv.y = acc[i][1] + b[1];
        hv.z = acc[i][2] + b[2];
        hv.w = acc[i][3] + b[3];
        *(float4*)&g_hpre[node * 128 + tx * 4] = hv;
        ps[0] += hv.x; ps[1] += hv.y; ps[2] += hv.z; ps[3] += hv.w;
        pss[0] += hv.x * hv.x; pss[1] += hv.y * hv.y;
        pss[2] += hv.z * hv.z; pss[3] += hv.w * hv.w;
    }
    #pragma unroll
    for (int j = 0; j < 4; j++) {
        atomicAdd(&s_sh[tx * 4 + j], ps[j]);
        atomicAdd(&ss_sh[tx * 4 + j], pss[j]);
    }
    __syncthreads();
    if (t < 128) {
        atomicAdd(&g_s1[t], s_sh[t]);
        atomicAdd(&g_ss1[t], ss_sh[t]);
    }
}

// ---------------- K3: BN1+ReLU fused with layer-2 GEMMs ----------------
// h = relu(bn1(hpre)); t2 = h@Wl2^T; p2 = h@Wr2^T + bl2
__global__ __launch_bounds__(256) void layer2_kernel(const float* __restrict__ Wl2,
                                                     const float* __restrict__ bl2,
                                                     const float* __restrict__ Wr2,
                                                     const float* __restrict__ g1,
                                                     const float* __restrict__ b1) {
    __shared__ float in_s[32][128];
    __shared__ float w_s[32][132];

    int t = threadIdx.x;
    int node0 = blockIdx.x * 32;
    const float invN = 1.0f / (float)NN;

    for (int idx = t; idx < 32 * 128; idx += 256) {
        int ni = idx >> 7, k = idx & 127;
        int node = node0 + ni;
        float mu = g_s1[k] * invN;
        float var = g_ss1[k] * invN - mu * mu;
        float v = g_hpre[node * 128 + k];
        v = g1[k] * (v - mu) * rsqrtf(var + EPSF) + b1[k];
        in_s[ni][k] = fmaxf(v, 0.f);
    }

    int tx = t & 31, ty = t >> 5;
    float acc[4][4] = {};

    for (int kc = 0; kc < 4; kc++) {
        __syncthreads();
        for (int idx = t; idx < 32 * 128; idx += 256) {
            int o = idx >> 5, kk = idx & 31;
            int kt = kc * 32 + kk;
            float wv = (o < 64) ? Wl2[o * 128 + kt] : Wr2[(o - 64) * 128 + kt];
            w_s[kk][o] = wv;
        }
        __syncthreads();
        #pragma unroll
        for (int kk = 0; kk < 32; kk++) {
            float4 wv4 = *(const float4*)&w_s[kk][tx * 4];
            float w[4] = {wv4.x, wv4.y, wv4.z, wv4.w};
            int kt = kc * 32 + kk;
            float a[4];
            #pragma unroll
            for (int i = 0; i < 4; i++) a[i] = in_s[ty * 4 + i][kt];
            #pragma unroll
            for (int i = 0; i < 4; i++)
                #pragma unroll
                for (int j = 0; j < 4; j++) acc[i][j] += a[i] * w[j];
        }
    }

    #pragma unroll
    for (int i = 0; i < 4; i++) {
        int node = node0 + ty * 4 + i;
        if (tx < 16) {
            float4 v = make_float4(acc[i][0], acc[i][1], acc[i][2], acc[i][3]);
            *(float4*)&g_t2[node * 64 + tx * 4] = v;
        } else {
            int o0 = tx * 4 - 64;
            float4 v = make_float4(acc[i][0] + bl2[o0],
                                   acc[i][1] + bl2[o0 + 1],
                                   acc[i][2] + bl2[o0 + 2],
                                   acc[i][3] + bl2[o0 + 3]);
            *(float4*)&g_p2[node * 64 + o0] = v;
        }
    }
}

// ---------------- K4: scatter t2 -> agg2 ----------------
__global__ __launch_bounds__(256) void scatter2_kernel(const int* __restrict__ ei) {
    long long tid = (long long)blockIdx.x * 256 + threadIdx.x;
    int e = (int)(tid >> 6);
    if (e >= NE) return;
    int c = (int)(tid & 63);
    int s, d;
    if (g_is64) { s = ei[2 * e]; d = ei[2 * (NE + e)]; }
    else        { s = ei[e];     d = ei[NE + e]; }
    atomicAdd(&g_agg2[d * 64 + c], g_t2[s * 64 + c]);
}

// ---------------- K5: x0pre = agg2/deg + p2, BN2 stats ----------------
__global__ __launch_bounds__(256) void x0pre_kernel() {
    int c = threadIdx.x & 63;
    int nl = threadIdx.x >> 6;  // 0..3
    float s = 0.f, ss = 0.f;
    for (int node = blockIdx.x * 4 + nl; node < NN; node += gridDim.x * 4) {
        float d = g_deg[node];
        float v = g_agg2[node * 64 + c] / fmaxf(d, 1.0f) + g_p2[node * 64 + c];
        g_x0pre[node * 64 + c] = v;
        s += v;
        ss += v * v;
    }
    __shared__ float shs[4][64], shss[4][64];
    shs[nl][c] = s;
    shss[nl][c] = ss;
    __syncthreads();
    if (nl == 0) {
        float S = shs[0][c] + shs[1][c] + shs[2][c] + shs[3][c];
        float SS = shss[0][c] + shss[1][c] + shss[2][c] + shss[3][c];
        atomicAdd(&g_s2[c], S);
        atomicAdd(&g_ss2[c], SS);
    }
}

// ---------------- K6: BN2+ReLU -> x0 out; fc + softmax -> x1 out ----------------
__global__ __launch_bounds__(256) void final_kernel(float* __restrict__ out,
                                                    const float* __restrict__ g2,
                                                    const float* __restrict__ b2,
                                                    const float* __restrict__ Wfc,
                                                    const float* __restrict__ bfc) {
    int node = blockIdx.x * 8 + (threadIdx.x >> 5);
    int lane = threadIdx.x & 31;
    if (node >= NN) return;
    const float invN = 1.0f / (float)NN;
    float x0v[2];
    #pragma unroll
    for (int j = 0; j < 2; j++) {
        int c = lane + 32 * j;
        float mu = g_s2[c] * invN;
        float var = g_ss2[c] * invN - mu * mu;
        float v = g_x0pre[node * 64 + c];
        v = g2[c] * (v - mu) * rsqrtf(var + EPSF) + b2[c];
        v = fmaxf(v, 0.f);
        x0v[j] = v;
        out[node * 64 + c] = v;
    }
    float l0 = x0v[0] * Wfc[lane] + x0v[1] * Wfc[lane + 32];
    float l1 = x0v[0] * Wfc[64 + lane] + x0v[1] * Wfc[96 + lane];
    #pragma unroll
    for (int o = 16; o; o >>= 1) {
        l0 += __shfl_down_sync(0xFFFFFFFFu, l0, o);
        l1 += __shfl_down_sync(0xFFFFFFFFu, l1, o);
    }
    if (lane == 0) {
        l0 += bfc[0];
        l1 += bfc[1];
        float m = fmaxf(l0, l1);
        float e0 = __expf(l0 - m), e1 = __expf(l1 - m);
        float inv = 1.0f / (e0 + e1);
        out[NN * 64 + node * 2 + 0] = e0 * inv;
        out[NN * 64 + node * 2 + 1] = e1 * inv;
    }
}

// ---------------- launch ----------------
extern "C" void kernel_launch(void* const* d_in, const int* in_sizes, int n_in,
                              void* d_out, int out_size) {
    const float* x   = (const float*)d_in[0];
    const int*   ei  = (const int*)d_in[1];  // int32 or int64 (runtime-detected)
    const float* Wl1 = (const float*)d_in[2];
    const float* bl1 = (const float*)d_in[3];
    const float* Wr1 = (const float*)d_in[4];
    const float* g1  = (const float*)d_in[5];
    const float* b1  = (const float*)d_in[6];
    const float* Wl2 = (const float*)d_in[7];
    const float* bl2 = (const float*)d_in[8];
    const float* Wr2 = (const float*)d_in[9];
    const float* g2  = (const float*)d_in[10];
    const float* b2  = (const float*)d_in[11];
    const float* Wfc = (const float*)d_in[12];
    const float* bfc = (const float*)d_in[13];
    float* out = (float*)d_out;

    zero_kernel<<<2048, 256>>>(ei);
    scatter1_kernel<<<(NE * 64 + 255) / 256, 256>>>(x, ei);
    layer1_kernel<<<NN / 32, 256>>>(x, Wl1, bl1, Wr1);
    layer2_kernel<<<NN / 32, 256>>>(Wl2, bl2, Wr2, g1, b1);
    scatter2_kernel<<<(NE * 64 + 255) / 256, 256>>>(ei);
    x0pre_kernel<<<1024, 256>>>();
    final_kernel<<<NN / 8, 256>>>(out, g2, b2, Wfc, bfc);
}

// round 2
// speedup vs baseline: 2.0301x; 2.0301x over previous
#include <cuda_runtime.h>

#define NN 100000
#define NE 1200000
#define EPSF 1e-5f

// ---------------- scratch (device globals; no allocations) ----------------
__device__ float g_deg[NN];
__device__ float g_agg1[NN * 64];
__device__ float g_hpre[NN * 128];
__device__ float g_t2[NN * 64];
__device__ float g_p2[NN * 64];
__device__ float g_agg2[NN * 64];
__device__ float g_x0pre[NN * 64];
__device__ float g_s1[128], g_ss1[128];
__device__ float g_s2[64], g_ss2[64];
__device__ float g_W1T[128 * 128];   // [k][o] transposed concat(Wl1|Wr1)
__device__ float g_W2T[128 * 128];   // [k][o] transposed concat(Wl2|Wr2)
__device__ int g_is64;

// ---------------- K0: zero scratch + weight transpose + dtype detect ----------------
__global__ void zero_kernel(const int* __restrict__ ei,
                            const float* __restrict__ Wl1, const float* __restrict__ Wr1,
                            const float* __restrict__ Wl2, const float* __restrict__ Wr2) {
    int i = blockIdx.x * blockDim.x + threadIdx.x;
    int stride = gridDim.x * blockDim.x;
    float4 z = make_float4(0.f, 0.f, 0.f, 0.f);
    for (int j = i; j < NN * 16; j += stride) {
        ((float4*)g_agg1)[j] = z;
        ((float4*)g_agg2)[j] = z;
    }
    for (int j = i; j < NN / 4; j += stride) ((float4*)g_deg)[j] = z;
    if (i < 16384) {
        int k = i >> 7, o = i & 127;
        g_W1T[i] = (k < 64) ? Wl1[o * 64 + k] : Wr1[o * 64 + (k - 64)];
        g_W2T[i] = (o < 64) ? Wl2[o * 128 + k] : Wr2[(o - 64) * 128 + k];
    }
    if (i < 128) { g_s1[i] = 0.f; g_ss1[i] = 0.f; }
    if (i < 64)  { g_s2[i] = 0.f; g_ss2[i] = 0.f; }
    if (i == 0) {
        int z2 = 0;
        #pragma unroll
        for (int k = 1; k < 16; k += 2) z2 |= ei[k];
        g_is64 = (z2 == 0) ? 1 : 0;
    }
}

// ---------------- vector reduction helper ----------------
__device__ __forceinline__ void red_add_v4(float* p, float4 v) {
    asm volatile("red.global.add.v4.f32 [%0], {%1,%2,%3,%4};"
                 :: "l"(p), "f"(v.x), "f"(v.y), "f"(v.z), "f"(v.w) : "memory");
}

// ---------------- K1: scatter x -> agg1, degree (16 threads/edge) ----------------
__global__ __launch_bounds__(256) void scatter1_kernel(const float* __restrict__ x,
                                                       const int* __restrict__ ei) {
    long long tid = (long long)blockIdx.x * 256 + threadIdx.x;
    int e = (int)(tid >> 4);
    if (e >= NE) return;
    int q = (int)(tid & 15);
    int s, d;
    if (g_is64) { s = ei[2 * e]; d = ei[2 * (NE + e)]; }
    else        { s = ei[e];     d = ei[NE + e]; }
    float4 v = *(const float4*)(x + (long long)s * 64 + q * 4);
    red_add_v4(&g_agg1[(long long)d * 64 + q * 4], v);
    if (q == 0) atomicAdd(&g_deg[d], 1.0f);
}

// ---------------- K2: layer-1 GEMMs + bias + BN1 stats ----------------
// hpre[i][o] = sum_k in[i][k]*W1T[k][o] + bl1[o], in = mean1||x
__global__ __launch_bounds__(256) void layer1_kernel(const float* __restrict__ x,
                                                     const float* __restrict__ bl1) {
    __shared__ float in_s[64][128];
    __shared__ float w_s[16][128];
    __shared__ float s_sh[128], ss_sh[128];
    __shared__ float inv_sh[64];

    int t = threadIdx.x;
    int node0 = blockIdx.x * 64;
    if (t < 128) { s_sh[t] = 0.f; ss_sh[t] = 0.f; }
    if (t < 64) {
        int n = node0 + t;
        inv_sh[t] = (n < NN) ? 1.0f / fmaxf(g_deg[n], 1.0f) : 0.f;
    }
    __syncthreads();

    for (int idx = t; idx < 64 * 32; idx += 256) {
        int ni = idx >> 5, k4 = idx & 31;
        int node = node0 + ni;
        float4 v = make_float4(0.f, 0.f, 0.f, 0.f);
        if (node < NN) {
            if (k4 < 16) {
                v = *(const float4*)&g_agg1[(size_t)node * 64 + k4 * 4];
                float s = inv_sh[ni];
                v.x *= s; v.y *= s; v.z *= s; v.w *= s;
            } else {
                v = *(const float4*)&x[(size_t)node * 64 + (k4 - 16) * 4];
            }
        }
        *(float4*)&in_s[ni][k4 * 4] = v;
    }

    int tx = t & 15, ty = t >> 4;
    float acc[4][8] = {};

    for (int kc = 0; kc < 8; kc++) {
        __syncthreads();
        for (int idx = t; idx < 16 * 32; idx += 256) {
            int kk = idx >> 5, o4 = idx & 31;
            *(float4*)&w_s[kk][o4 * 4] =
                *(const float4*)&g_W1T[(kc * 16 + kk) * 128 + o4 * 4];
        }
        __syncthreads();
        #pragma unroll
        for (int kk = 0; kk < 16; kk++) {
            int kt = kc * 16 + kk;
            float4 w0 = *(const float4*)&w_s[kk][tx * 4];
            float4 w1 = *(const float4*)&w_s[kk][64 + tx * 4];
            #pragma unroll
            for (int i = 0; i < 4; i++) {
                float a = in_s[ty * 4 + i][kt];
                acc[i][0] += a * w0.x; acc[i][1] += a * w0.y;
                acc[i][2] += a * w0.z; acc[i][3] += a * w0.w;
                acc[i][4] += a * w1.x; acc[i][5] += a * w1.y;
                acc[i][6] += a * w1.z; acc[i][7] += a * w1.w;
            }
        }
    }

    float4 bA = *(const float4*)&bl1[tx * 4];
    float4 bB = *(const float4*)&bl1[64 + tx * 4];
    float ps[8] = {}, pss[8] = {};
    #pragma unroll
    for (int i = 0; i < 4; i++) {
        int node = node0 + ty * 4 + i;
        if (node >= NN) continue;
        float h[8];
        h[0] = acc[i][0] + bA.x; h[1] = acc[i][1] + bA.y;
        h[2] = acc[i][2] + bA.z; h[3] = acc[i][3] + bA.w;
        h[4] = acc[i][4] + bB.x; h[5] = acc[i][5] + bB.y;
        h[6] = acc[i][6] + bB.z; h[7] = acc[i][7] + bB.w;
        *(float4*)&g_hpre[(size_t)node * 128 + tx * 4] = make_float4(h[0], h[1], h[2], h[3]);
        *(float4*)&g_hpre[(size_t)node * 128 + 64 + tx * 4] = make_float4(h[4], h[5], h[6], h[7]);
        #pragma unroll
        for (int j = 0; j < 8; j++) { ps[j] += h[j]; pss[j] += h[j] * h[j]; }
    }
    #pragma unroll
    for (int j = 0; j < 4; j++) {
        atomicAdd(&s_sh[tx * 4 + j], ps[j]);
        atomicAdd(&ss_sh[tx * 4 + j], pss[j]);
        atomicAdd(&s_sh[64 + tx * 4 + j], ps[4 + j]);
        atomicAdd(&ss_sh[64 + tx * 4 + j], pss[4 + j]);
    }
    __syncthreads();
    if (t < 128) {
        atomicAdd(&g_s1[t], s_sh[t]);
        atomicAdd(&g_ss1[t], ss_sh[t]);
    }
}

// ---------------- K3: BN1+ReLU fused with layer-2 GEMMs ----------------
__global__ __launch_bounds__(256) void layer2_kernel(const float* __restrict__ bl2,
                                                     const float* __restrict__ g1,
                                                     const float* __restrict__ b1) {
    __shared__ float in_s[64][128];
    __shared__ float w_s[16][128];
    __shared__ float sc_sh[128], sh_sh[128];

    int t = threadIdx.x;
    int node0 = blockIdx.x * 64;
    const float invN = 1.0f / (float)NN;

    if (t < 128) {
        float mu = g_s1[t] * invN;
        float var = g_ss1[t] * invN - mu * mu;
        float sc = g1[t] * rsqrtf(var + EPSF);
        sc_sh[t] = sc;
        sh_sh[t] = b1[t] - mu * sc;
    }
    __syncthreads();

    for (int idx = t; idx < 64 * 32; idx += 256) {
        int ni = idx >> 5, k4 = idx & 31;
        int node = node0 + ni;
        float4 v = make_float4(0.f, 0.f, 0.f, 0.f);
        if (node < NN) {
            v = *(const float4*)&g_hpre[(size_t)node * 128 + k4 * 4];
            int c = k4 * 4;
            v.x = fmaxf(v.x * sc_sh[c] + sh_sh[c], 0.f);
            v.y = fmaxf(v.y * sc_sh[c + 1] + sh_sh[c + 1], 0.f);
            v.z = fmaxf(v.z * sc_sh[c + 2] + sh_sh[c + 2], 0.f);
            v.w = fmaxf(v.w * sc_sh[c + 3] + sh_sh[c + 3], 0.f);
        }
        *(float4*)&in_s[ni][k4 * 4] = v;
    }

    int tx = t & 15, ty = t >> 4;
    float acc[4][8] = {};

    for (int kc = 0; kc < 8; kc++) {
        __syncthreads();
        for (int idx = t; idx < 16 * 32; idx += 256) {
            int kk = idx >> 5, o4 = idx & 31;
            *(float4*)&w_s[kk][o4 * 4] =
                *(const float4*)&g_W2T[(kc * 16 + kk) * 128 + o4 * 4];
        }
        __syncthreads();
        #pragma unroll
        for (int kk = 0; kk < 16; kk++) {
            int kt = kc * 16 + kk;
            float4 w0 = *(const float4*)&w_s[kk][tx * 4];
            float4 w1 = *(const float4*)&w_s[kk][64 + tx * 4];
            #pragma unroll
            for (int i = 0; i < 4; i++) {
                float a = in_s[ty * 4 + i][kt];
                acc[i][0] += a * w0.x; acc[i][1] += a * w0.y;
                acc[i][2] += a * w0.z; acc[i][3] += a * w0.w;
                acc[i][4] += a * w1.x; acc[i][5] += a * w1.y;
                acc[i][6] += a * w1.z; acc[i][7] += a * w1.w;
            }
        }
    }

    float4 bB = *(const float4*)&bl2[tx * 4];
    #pragma unroll
    for (int i = 0; i < 4; i++) {
        int node = node0 + ty * 4 + i;
        if (node >= NN) continue;
        // outs 0..63 -> t2 (no bias); outs 64..127 -> p2 + bl2
        *(float4*)&g_t2[(size_t)node * 64 + tx * 4] =
            make_float4(acc[i][0], acc[i][1], acc[i][2], acc[i][3]);
        *(float4*)&g_p2[(size_t)node * 64 + tx * 4] =
            make_float4(acc[i][4] + bB.x, acc[i][5] + bB.y,
                        acc[i][6] + bB.z, acc[i][7] + bB.w);
    }
}

// ---------------- K4: scatter t2 -> agg2 (16 threads/edge) ----------------
__global__ __launch_bounds__(256) void scatter2_kernel(const int* __restrict__ ei) {
    long long tid = (long long)blockIdx.x * 256 + threadIdx.x;
    int e = (int)(tid >> 4);
    if (e >= NE) return;
    int q = (int)(tid & 15);
    int s, d;
    if (g_is64) { s = ei[2 * e]; d = ei[2 * (NE + e)]; }
    else        { s = ei[e];     d = ei[NE + e]; }
    float4 v = *(const float4*)&g_t2[(long long)s * 64 + q * 4];
    red_add_v4(&g_agg2[(long long)d * 64 + q * 4], v);
}

// ---------------- K5: x0pre = agg2/deg + p2, BN2 stats ----------------
__global__ __launch_bounds__(256) void x0pre_kernel() {
    int t = threadIdx.x;
    int c4 = t & 15, nl = t >> 4;  // 16 f4-channels x 16 node-lanes
    float4 s = make_float4(0.f, 0.f, 0.f, 0.f);
    float4 ss = make_float4(0.f, 0.f, 0.f, 0.f);
    for (int node = blockIdx.x * 16 + nl; node < NN; node += gridDim.x * 16) {
        float invd = 1.0f / fmaxf(g_deg[node], 1.0f);
        float4 a = *(const float4*)&g_agg2[(size_t)node * 64 + c4 * 4];
        float4 p = *(const float4*)&g_p2[(size_t)node * 64 + c4 * 4];
        float4 v = make_float4(a.x * invd + p.x, a.y * invd + p.y,
                               a.z * invd + p.z, a.w * invd + p.w);
        *(float4*)&g_x0pre[(size_t)node * 64 + c4 * 4] = v;
        s.x += v.x; s.y += v.y; s.z += v.z; s.w += v.w;
        ss.x += v.x * v.x; ss.y += v.y * v.y; ss.z += v.z * v.z; ss.w += v.w * v.w;
    }
    __shared__ float shs[16][64], shss[16][64];
    shs[nl][c4 * 4] = s.x; shs[nl][c4 * 4 + 1] = s.y;
    shs[nl][c4 * 4 + 2] = s.z; shs[nl][c4 * 4 + 3] = s.w;
    shss[nl][c4 * 4] = ss.x; shss[nl][c4 * 4 + 1] = ss.y;
    shss[nl][c4 * 4 + 2] = ss.z; shss[nl][c4 * 4 + 3] = ss.w;
    __syncthreads();
    if (t < 64) {
        float S = 0.f, SS = 0.f;
        #pragma unroll
        for (int j = 0; j < 16; j++) { S += shs[j][t]; SS += shss[j][t]; }
        atomicAdd(&g_s2[t], S);
        atomicAdd(&g_ss2[t], SS);
    }
}

// ---------------- K6: BN2+ReLU -> x0 out; fc + softmax -> x1 out ----------------
__global__ __launch_bounds__(256) void final_kernel(float* __restrict__ out,
                                                    const float* __restrict__ g2,
                                                    const float* __restrict__ b2,
                                                    const float* __restrict__ Wfc,
                                                    const float* __restrict__ bfc) {
    int node = blockIdx.x * 8 + (threadIdx.x >> 5);
    int lane = threadIdx.x & 31;
    if (node >= NN) return;
    const float invN = 1.0f / (float)NN;
    float x0v[2];
    #pragma unroll
    for (int j = 0; j < 2; j++) {
        int c = lane + 32 * j;
        float mu = g_s2[c] * invN;
        float var = g_ss2[c] * invN - mu * mu;
        float v = g_x0pre[(size_t)node * 64 + c];
        v = g2[c] * (v - mu) * rsqrtf(var + EPSF) + b2[c];
        v = fmaxf(v, 0.f);
        x0v[j] = v;
        out[(size_t)node * 64 + c] = v;
    }
    float l0 = x0v[0] * Wfc[lane] + x0v[1] * Wfc[lane + 32];
    float l1 = x0v[0] * Wfc[64 + lane] + x0v[1] * Wfc[96 + lane];
    #pragma unroll
    for (int o = 16; o; o >>= 1) {
        l0 += __shfl_down_sync(0xFFFFFFFFu, l0, o);
        l1 += __shfl_down_sync(0xFFFFFFFFu, l1, o);
    }
    if (lane == 0) {
        l0 += bfc[0];
        l1 += bfc[1];
        float m = fmaxf(l0, l1);
        float e0 = __expf(l0 - m), e1 = __expf(l1 - m);
        float inv = 1.0f / (e0 + e1);
        out[(size_t)NN * 64 + node * 2 + 0] = e0 * inv;
        out[(size_t)NN * 64 + node * 2 + 1] = e1 * inv;
    }
}

// ---------------- launch ----------------
extern "C" void kernel_launch(void* const* d_in, const int* in_sizes, int n_in,
                              void* d_out, int out_size) {
    const float* x   = (const float*)d_in[0];
    const int*   ei  = (const int*)d_in[1];
    const float* Wl1 = (const float*)d_in[2];
    const float* bl1 = (const float*)d_in[3];
    const float* Wr1 = (const float*)d_in[4];
    const float* g1  = (const float*)d_in[5];
    const float* b1  = (const float*)d_in[6];
    const float* Wl2 = (const float*)d_in[7];
    const float* bl2 = (const float*)d_in[8];
    const float* Wr2 = (const float*)d_in[9];
    const float* g2  = (const float*)d_in[10];
    const float* b2  = (const float*)d_in[11];
    const float* Wfc = (const float*)d_in[12];
    const float* bfc = (const float*)d_in[13];
    float* out = (float*)d_out;

    zero_kernel<<<4096, 256>>>(ei, Wl1, Wr1, Wl2, Wr2);
    scatter1_kernel<<<(NE * 16 + 255) / 256, 256>>>(x, ei);
    layer1_kernel<<<(NN + 63) / 64, 256>>>(x, bl1);
    layer2_kernel<<<(NN + 63) / 64, 256>>>(bl2, g1, b1);
    scatter2_kernel<<<(NE * 16 + 255) / 256, 256>>>(ei);
    x0pre_kernel<<<1024, 256>>>();
    final_kernel<<<(NN + 7) / 8, 256>>>(out, g2, b2, Wfc, bfc);
}

// round 3
// speedup vs baseline: 2.3093x; 1.1375x over previous
#include <cuda_runtime.h>

#define NN 100000
#define NE 1200000
#define EPSF 1e-5f
#define NBLK 391  // ceil(NN/256)

// ---------------- scratch (device globals; no allocations) ----------------
__device__ int   g_cnt[NN];
__device__ int   g_rowptr[NN + 1];
__device__ int   g_cursor[NN];
__device__ int   g_blocksum[NBLK];
__device__ int   g_blockoff[NBLK];
__device__ int   g_csr[NE];
__device__ float g_agg1[NN * 64];
__device__ float g_hpre[NN * 128];
__device__ float g_t2[NN * 64];
__device__ float g_p2[NN * 64];
__device__ float g_x0pre[NN * 64];
__device__ float g_s1[128], g_ss1[128];
__device__ float g_s2[64], g_ss2[64];
__device__ float g_W1T[128 * 128];
__device__ float g_W2T[128 * 128];
__device__ int   g_is64;

// ---------------- K0: zero + weight transpose + dtype detect ----------------
__global__ void init_kernel(const int* __restrict__ ei,
                            const float* __restrict__ Wl1, const float* __restrict__ Wr1,
                            const float* __restrict__ Wl2, const float* __restrict__ Wr2) {
    int i = blockIdx.x * blockDim.x + threadIdx.x;
    int stride = gridDim.x * blockDim.x;
    for (int j = i; j < NN; j += stride) g_cnt[j] = 0;
    if (i < 16384) {
        int k = i >> 7, o = i & 127;
        g_W1T[i] = (k < 64) ? Wl1[o * 64 + k] : Wr1[o * 64 + (k - 64)];
        g_W2T[i] = (o < 64) ? Wl2[o * 128 + k] : Wr2[(o - 64) * 128 + k];
    }
    if (i < 128) { g_s1[i] = 0.f; g_ss1[i] = 0.f; }
    if (i < 64)  { g_s2[i] = 0.f; g_ss2[i] = 0.f; }
    if (i == 0) {
        int z = 0;
        #pragma unroll
        for (int k = 1; k < 16; k += 2) z |= ei[k];
        g_is64 = (z == 0) ? 1 : 0;
    }
}

// ---------------- K1: histogram of dst ----------------
__global__ __launch_bounds__(256) void hist_kernel(const int* __restrict__ ei) {
    int e = blockIdx.x * 256 + threadIdx.x;
    if (e >= NE) return;
    int d = g_is64 ? ei[2 * (NE + e)] : ei[NE + e];
    atomicAdd(&g_cnt[d], 1);
}

// ---------------- K2a/b/c: two-level exclusive scan -> row_ptr ----------------
__global__ __launch_bounds__(256) void scan_a_kernel() {
    __shared__ int s[256];
    int t = threadIdx.x;
    int i = blockIdx.x * 256 + t;
    s[t] = (i < NN) ? g_cnt[i] : 0;
    __syncthreads();
    for (int off = 128; off; off >>= 1) {
        if (t < off) s[t] += s[t + off];
        __syncthreads();
    }
    if (t == 0) g_blocksum[blockIdx.x] = s[0];
}

__global__ __launch_bounds__(512) void scan_b_kernel() {
    __shared__ int s[512];
    int t = threadIdx.x;
    int v = (t < NBLK) ? g_blocksum[t] : 0;
    s[t] = v;
    __syncthreads();
    for (int off = 1; off < 512; off <<= 1) {
        int x = (t >= off) ? s[t - off] : 0;
        __syncthreads();
        s[t] += x;
        __syncthreads();
    }
    if (t < NBLK) g_blockoff[t] = s[t] - v;
}

__global__ __launch_bounds__(256) void scan_c_kernel() {
    __shared__ int s[256];
    int t = threadIdx.x;
    int i = blockIdx.x * 256 + t;
    int v = (i < NN) ? g_cnt[i] : 0;
    s[t] = v;
    __syncthreads();
    for (int off = 1; off < 256; off <<= 1) {
        int x = (t >= off) ? s[t - off] : 0;
        __syncthreads();
        s[t] += x;
        __syncthreads();
    }
    int excl = g_blockoff[blockIdx.x] + s[t] - v;
    if (i < NN) { g_rowptr[i] = excl; g_cursor[i] = excl; }
    if (i == 0) g_rowptr[NN] = NE;
}

// ---------------- K3: fill CSR src lists ----------------
__global__ __launch_bounds__(256) void fill_kernel(const int* __restrict__ ei) {
    int e = blockIdx.x * 256 + threadIdx.x;
    if (e >= NE) return;
    int s, d;
    if (g_is64) { s = ei[2 * e]; d = ei[2 * (NE + e)]; }
    else        { s = ei[e];     d = ei[NE + e]; }
    int pos = atomicAdd(&g_cursor[d], 1);
    g_csr[pos] = s;
}

// ---------------- K4: aggregate x -> agg1 (warp per node) ----------------
__global__ __launch_bounds__(256) void agg1_kernel(const float* __restrict__ x) {
    int node = (blockIdx.x * 256 + threadIdx.x) >> 5;
    if (node >= NN) return;
    int lane = threadIdx.x & 31;
    int c4 = lane & 15, half = lane >> 4;
    int start = g_rowptr[node], end = g_rowptr[node + 1];
    float4 acc = make_float4(0.f, 0.f, 0.f, 0.f);
    for (int e = start + half; e < end; e += 2) {
        int s = __ldg(&g_csr[e]);
        float4 v = *(const float4*)&x[(size_t)s * 64 + c4 * 4];
        acc.x += v.x; acc.y += v.y; acc.z += v.z; acc.w += v.w;
    }
    acc.x += __shfl_xor_sync(0xFFFFFFFFu, acc.x, 16);
    acc.y += __shfl_xor_sync(0xFFFFFFFFu, acc.y, 16);
    acc.z += __shfl_xor_sync(0xFFFFFFFFu, acc.z, 16);
    acc.w += __shfl_xor_sync(0xFFFFFFFFu, acc.w, 16);
    if (half == 0)
        *(float4*)&g_agg1[(size_t)node * 64 + c4 * 4] = acc;
}

// ---------------- K5: layer-1 GEMMs + bias + BN1 stats ----------------
__global__ __launch_bounds__(256) void layer1_kernel(const float* __restrict__ x,
                                                     const float* __restrict__ bl1) {
    __shared__ float in_s[64][128];
    __shared__ float w_s[16][128];
    __shared__ float s_sh[128], ss_sh[128];
    __shared__ float inv_sh[64];

    int t = threadIdx.x;
    int node0 = blockIdx.x * 64;
    if (t < 128) { s_sh[t] = 0.f; ss_sh[t] = 0.f; }
    if (t < 64) {
        int n = node0 + t;
        if (n < NN) {
            float d = (float)(g_rowptr[n + 1] - g_rowptr[n]);
            inv_sh[t] = 1.0f / fmaxf(d, 1.0f);
        } else inv_sh[t] = 0.f;
    }
    __syncthreads();

    for (int idx = t; idx < 64 * 32; idx += 256) {
        int ni = idx >> 5, k4 = idx & 31;
        int node = node0 + ni;
        float4 v = make_float4(0.f, 0.f, 0.f, 0.f);
        if (node < NN) {
            if (k4 < 16) {
                v = *(const float4*)&g_agg1[(size_t)node * 64 + k4 * 4];
                float s = inv_sh[ni];
                v.x *= s; v.y *= s; v.z *= s; v.w *= s;
            } else {
                v = *(const float4*)&x[(size_t)node * 64 + (k4 - 16) * 4];
            }
        }
        *(float4*)&in_s[ni][k4 * 4] = v;
    }

    int tx = t & 15, ty = t >> 4;
    float acc[4][8] = {};

    for (int kc = 0; kc < 8; kc++) {
        __syncthreads();
        for (int idx = t; idx < 16 * 32; idx += 256) {
            int kk = idx >> 5, o4 = idx & 31;
            *(float4*)&w_s[kk][o4 * 4] =
                *(const float4*)&g_W1T[(kc * 16 + kk) * 128 + o4 * 4];
        }
        __syncthreads();
        #pragma unroll
        for (int kk = 0; kk < 16; kk++) {
            int kt = kc * 16 + kk;
            float4 w0 = *(const float4*)&w_s[kk][tx * 4];
            float4 w1 = *(const float4*)&w_s[kk][64 + tx * 4];
            #pragma unroll
            for (int i = 0; i < 4; i++) {
                float a = in_s[ty * 4 + i][kt];
                acc[i][0] += a * w0.x; acc[i][1] += a * w0.y;
                acc[i][2] += a * w0.z; acc[i][3] += a * w0.w;
                acc[i][4] += a * w1.x; acc[i][5] += a * w1.y;
                acc[i][6] += a * w1.z; acc[i][7] += a * w1.w;
            }
        }
    }

    float4 bA = *(const float4*)&bl1[tx * 4];
    float4 bB = *(const float4*)&bl1[64 + tx * 4];
    float ps[8] = {}, pss[8] = {};
    #pragma unroll
    for (int i = 0; i < 4; i++) {
        int node = node0 + ty * 4 + i;
        if (node >= NN) continue;
        float h[8];
        h[0] = acc[i][0] + bA.x; h[1] = acc[i][1] + bA.y;
        h[2] = acc[i][2] + bA.z; h[3] = acc[i][3] + bA.w;
        h[4] = acc[i][4] + bB.x; h[5] = acc[i][5] + bB.y;
        h[6] = acc[i][6] + bB.z; h[7] = acc[i][7] + bB.w;
        *(float4*)&g_hpre[(size_t)node * 128 + tx * 4] = make_float4(h[0], h[1], h[2], h[3]);
        *(float4*)&g_hpre[(size_t)node * 128 + 64 + tx * 4] = make_float4(h[4], h[5], h[6], h[7]);
        #pragma unroll
        for (int j = 0; j < 8; j++) { ps[j] += h[j]; pss[j] += h[j] * h[j]; }
    }
    #pragma unroll
    for (int j = 0; j < 4; j++) {
        atomicAdd(&s_sh[tx * 4 + j], ps[j]);
        atomicAdd(&ss_sh[tx * 4 + j], pss[j]);
        atomicAdd(&s_sh[64 + tx * 4 + j], ps[4 + j]);
        atomicAdd(&ss_sh[64 + tx * 4 + j], pss[4 + j]);
    }
    __syncthreads();
    if (t < 128) {
        atomicAdd(&g_s1[t], s_sh[t]);
        atomicAdd(&g_ss1[t], ss_sh[t]);
    }
}

// ---------------- K6: BN1+ReLU fused with layer-2 GEMMs ----------------
__global__ __launch_bounds__(256) void layer2_kernel(const float* __restrict__ bl2,
                                                     const float* __restrict__ g1,
                                                     const float* __restrict__ b1) {
    __shared__ float in_s[64][128];
    __shared__ float w_s[16][128];
    __shared__ float sc_sh[128], sh_sh[128];

    int t = threadIdx.x;
    int node0 = blockIdx.x * 64;
    const float invN = 1.0f / (float)NN;

    if (t < 128) {
        float mu = g_s1[t] * invN;
        float var = g_ss1[t] * invN - mu * mu;
        float sc = g1[t] * rsqrtf(var + EPSF);
        sc_sh[t] = sc;
        sh_sh[t] = b1[t] - mu * sc;
    }
    __syncthreads();

    for (int idx = t; idx < 64 * 32; idx += 256) {
        int ni = idx >> 5, k4 = idx & 31;
        int node = node0 + ni;
        float4 v = make_float4(0.f, 0.f, 0.f, 0.f);
        if (node < NN) {
            v = *(const float4*)&g_hpre[(size_t)node * 128 + k4 * 4];
            int c = k4 * 4;
            v.x = fmaxf(v.x * sc_sh[c] + sh_sh[c], 0.f);
            v.y = fmaxf(v.y * sc_sh[c + 1] + sh_sh[c + 1], 0.f);
            v.z = fmaxf(v.z * sc_sh[c + 2] + sh_sh[c + 2], 0.f);
            v.w = fmaxf(v.w * sc_sh[c + 3] + sh_sh[c + 3], 0.f);
        }
        *(float4*)&in_s[ni][k4 * 4] = v;
    }

    int tx = t & 15, ty = t >> 4;
    float acc[4][8] = {};

    for (int kc = 0; kc < 8; kc++) {
        __syncthreads();
        for (int idx = t; idx < 16 * 32; idx += 256) {
            int kk = idx >> 5, o4 = idx & 31;
            *(float4*)&w_s[kk][o4 * 4] =
                *(const float4*)&g_W2T[(kc * 16 + kk) * 128 + o4 * 4];
        }
        __syncthreads();
        #pragma unroll
        for (int kk = 0; kk < 16; kk++) {
            int kt = kc * 16 + kk;
            float4 w0 = *(const float4*)&w_s[kk][tx * 4];
            float4 w1 = *(const float4*)&w_s[kk][64 + tx * 4];
            #pragma unroll
            for (int i = 0; i < 4; i++) {
                float a = in_s[ty * 4 + i][kt];
                acc[i][0] += a * w0.x; acc[i][1] += a * w0.y;
                acc[i][2] += a * w0.z; acc[i][3] += a * w0.w;
                acc[i][4] += a * w1.x; acc[i][5] += a * w1.y;
                acc[i][6] += a * w1.z; acc[i][7] += a * w1.w;
            }
        }
    }

    float4 bB = *(const float4*)&bl2[tx * 4];
    #pragma unroll
    for (int i = 0; i < 4; i++) {
        int node = node0 + ty * 4 + i;
        if (node >= NN) continue;
        *(float4*)&g_t2[(size_t)node * 64 + tx * 4] =
            make_float4(acc[i][0], acc[i][1], acc[i][2], acc[i][3]);
        *(float4*)&g_p2[(size_t)node * 64 + tx * 4] =
            make_float4(acc[i][4] + bB.x, acc[i][5] + bB.y,
                        acc[i][6] + bB.z, acc[i][7] + bB.w);
    }
}

// ---------------- K7: aggregate t2 + mean + p2 -> x0pre, BN2 stats ----------------
__global__ __launch_bounds__(256) void agg2_kernel() {
    __shared__ float s2s[64], ss2s[64];
    int t = threadIdx.x;
    if (t < 64) { s2s[t] = 0.f; ss2s[t] = 0.f; }
    __syncthreads();

    int node = (blockIdx.x * 256 + t) >> 5;
    int lane = t & 31;
    int c4 = lane & 15, half = lane >> 4;
    if (node < NN) {
        int start = g_rowptr[node], end = g_rowptr[node + 1];
        float4 acc = make_float4(0.f, 0.f, 0.f, 0.f);
        for (int e = start + half; e < end; e += 2) {
            int s = __ldg(&g_csr[e]);
            float4 v = *(const float4*)&g_t2[(size_t)s * 64 + c4 * 4];
            acc.x += v.x; acc.y += v.y; acc.z += v.z; acc.w += v.w;
        }
        acc.x += __shfl_xor_sync(0xFFFFFFFFu, acc.x, 16);
        acc.y += __shfl_xor_sync(0xFFFFFFFFu, acc.y, 16);
        acc.z += __shfl_xor_sync(0xFFFFFFFFu, acc.z, 16);
        acc.w += __shfl_xor_sync(0xFFFFFFFFu, acc.w, 16);
        if (half == 0) {
            float invd = 1.0f / fmaxf((float)(end - start), 1.0f);
            float4 p = *(const float4*)&g_p2[(size_t)node * 64 + c4 * 4];
            float4 v = make_float4(acc.x * invd + p.x, acc.y * invd + p.y,
                                   acc.z * invd + p.z, acc.w * invd + p.w);
            *(float4*)&g_x0pre[(size_t)node * 64 + c4 * 4] = v;
            atomicAdd(&s2s[c4 * 4 + 0], v.x);
            atomicAdd(&s2s[c4 * 4 + 1], v.y);
            atomicAdd(&s2s[c4 * 4 + 2], v.z);
            atomicAdd(&s2s[c4 * 4 + 3], v.w);
            atomicAdd(&ss2s[c4 * 4 + 0], v.x * v.x);
            atomicAdd(&ss2s[c4 * 4 + 1], v.y * v.y);
            atomicAdd(&ss2s[c4 * 4 + 2], v.z * v.z);
            atomicAdd(&ss2s[c4 * 4 + 3], v.w * v.w);
        }
    }
    __syncthreads();
    if (t < 64) {
        atomicAdd(&g_s2[t], s2s[t]);
        atomicAdd(&g_ss2[t], ss2s[t]);
    }
}

// ---------------- K8: BN2+ReLU -> x0 out; fc + softmax -> x1 out ----------------
__global__ __launch_bounds__(256) void final_kernel(float* __restrict__ out,
                                                    const float* __restrict__ g2,
                                                    const float* __restrict__ b2,
                                                    const float* __restrict__ Wfc,
                                                    const float* __restrict__ bfc) {
    int node = blockIdx.x * 8 + (threadIdx.x >> 5);
    int lane = threadIdx.x & 31;
    if (node >= NN) return;
    const float invN = 1.0f / (float)NN;
    float x0v[2];
    #pragma unroll
    for (int j = 0; j < 2; j++) {
        int c = lane + 32 * j;
        float mu = g_s2[c] * invN;
        float var = g_ss2[c] * invN - mu * mu;
        float v = g_x0pre[(size_t)node * 64 + c];
        v = g2[c] * (v - mu) * rsqrtf(var + EPSF) + b2[c];
        v = fmaxf(v, 0.f);
        x0v[j] = v;
        out[(size_t)node * 64 + c] = v;
    }
    float l0 = x0v[0] * Wfc[lane] + x0v[1] * Wfc[lane + 32];
    float l1 = x0v[0] * Wfc[64 + lane] + x0v[1] * Wfc[96 + lane];
    #pragma unroll
    for (int o = 16; o; o >>= 1) {
        l0 += __shfl_down_sync(0xFFFFFFFFu, l0, o);
        l1 += __shfl_down_sync(0xFFFFFFFFu, l1, o);
    }
    if (lane == 0) {
        l0 += bfc[0];
        l1 += bfc[1];
        float m = fmaxf(l0, l1);
        float e0 = __expf(l0 - m), e1 = __expf(l1 - m);
        float inv = 1.0f / (e0 + e1);
        out[(size_t)NN * 64 + node * 2 + 0] = e0 * inv;
        out[(size_t)NN * 64 + node * 2 + 1] = e1 * inv;
    }
}

// ---------------- launch ----------------
extern "C" void kernel_launch(void* const* d_in, const int* in_sizes, int n_in,
                              void* d_out, int out_size) {
    const float* x   = (const float*)d_in[0];
    const int*   ei  = (const int*)d_in[1];
    const float* Wl1 = (const float*)d_in[2];
    const float* bl1 = (const float*)d_in[3];
    const float* Wr1 = (const float*)d_in[4];
    const float* g1  = (const float*)d_in[5];
    const float* b1  = (const float*)d_in[6];
    const float* Wl2 = (const float*)d_in[7];
    const float* bl2 = (const float*)d_in[8];
    const float* Wr2 = (const float*)d_in[9];
    const float* g2  = (const float*)d_in[10];
    const float* b2  = (const float*)d_in[11];
    const float* Wfc = (const float*)d_in[12];
    const float* bfc = (const float*)d_in[13];
    float* out = (float*)d_out;

    init_kernel<<<512, 256>>>(ei, Wl1, Wr1, Wl2, Wr2);
    hist_kernel<<<(NE + 255) / 256, 256>>>(ei);
    scan_a_kernel<<<NBLK, 256>>>();
    scan_b_kernel<<<1, 512>>>();
    scan_c_kernel<<<NBLK, 256>>>();
    fill_kernel<<<(NE + 255) / 256, 256>>>(ei);
    agg1_kernel<<<(NN * 32 + 255) / 256, 256>>>(x);
    layer1_kernel<<<(NN + 63) / 64, 256>>>(x, bl1);
    layer2_kernel<<<(NN + 63) / 64, 256>>>(bl2, g1, b1);
    agg2_kernel<<<(NN * 32 + 255) / 256, 256>>>();
    final_kernel<<<(NN + 7) / 8, 256>>>(out, g2, b2, Wfc, bfc);
}